// round 6
// baseline (speedup 1.0000x reference)
#include <cuda_runtime.h>
#include <math.h>

// Fused SNN spike layer, two-stage filtered streaming (R6: geometry + MLP).
//  L : 5 back-to-back predicated LDG.128 per thread (MLP=5), counts -> shared.
//  C : 16-chunk counts; rigorous overestimate u <= sum_d M[d]*cnt[C-d]
//      (M from actual srm taps). Refractory <= 0 => unflagged never spike.
//  Z : unflagged rows -> linear STG.128 zero-fill.
//  S2: flagged rows -> EXACT truncated-u recurrence max (no pending).
//      max u < theta => u_eff == u before any spike => output exactly zero.
//  S3: rows with max u >= theta -> full exact scan (R1/R2 arithmetic).

#define T_LEN    300
#define Q4       75
#define R        32            // rows per block
#define NTH      480           // 32*75/480 = 5 exact iters
#define ITERS    5
#define NCH16    19
#define CNTSTR   76            // Q4 + pad
#define CCSTR    20
#define PENDN    16
#define NDELTA   8
#define THETA    10.0f

__global__ __launch_bounds__(NTH, 2)
void snn_r6_kernel(const float* __restrict__ x,
                   const float* __restrict__ srm,
                   const float* __restrict__ refk,
                   float* __restrict__ out,
                   int B, int Ksrm, int Kref)
{
    __shared__ unsigned char cnt4[R * CNTSTR];
    __shared__ unsigned char cc[R * CCSTR];
    __shared__ unsigned char flag[R];
    __shared__ unsigned char list[R];
    __shared__ int nlist;
    __shared__ float s_M[NDELTA];
    __shared__ float s_rt[PENDN];

    const int tid  = threadIdx.x;
    const int row0 = blockIdx.x * R;
    const long long g4base = (long long)row0 * Q4;
    const long long g4tot  = (long long)B * Q4;

    if (tid < R) { flag[tid] = 0; cnt4[tid * CNTSTR + Q4] = 0; }
    if (tid == 0) nlist = 0;
    if (tid < PENDN) {
        float v = 0.0f;
        if (tid + 1 < Kref) v = refk[tid + 1];
        s_rt[tid] = v;
    }
    if (tid < NDELTA) {
        int lo = 16 * tid - 15; if (lo < 0) lo = 0;
        int hi = 16 * tid + 15; if (hi > Ksrm - 1) hi = Ksrm - 1;
        float m = 0.0f;
        for (int k = lo; k <= hi; ++k) m = fmaxf(m, srm[k]);
        s_M[tid] = m;
    }

    // ---- L: batched loads first (5 independent LDG.128 in flight) ----
    const float4* x4 = (const float4*)x;
    const float4 z = make_float4(0.f, 0.f, 0.f, 0.f);
    float4 v[ITERS];
#pragma unroll
    for (int it = 0; it < ITERS; ++it) {
        const long long g = g4base + it * NTH + tid;
        v[it] = (g < g4tot) ? x4[g] : z;
    }
    __syncthreads();   // covers the flag/pad/const init above
#pragma unroll
    for (int it = 0; it < ITERS; ++it) {
        const int idx = it * NTH + tid;
        const int r = idx / Q4;
        const int q = idx - r * Q4;
        const int c = (v[it].x != 0.0f) + (v[it].y != 0.0f)
                    + (v[it].z != 0.0f) + (v[it].w != 0.0f);
        cnt4[r * CNTSTR + q] = (unsigned char)c;
    }
    __syncthreads();

    // ---- C1: 16-chunk counts ----
    for (int i = tid; i < R * NCH16; i += NTH) {
        const int r = i / NCH16;
        const int c = i - r * NCH16;
        const unsigned char* b = cnt4 + r * CNTSTR + 4 * c;
        cc[r * CCSTR + c] = (unsigned char)(b[0] + b[1] + b[2] + b[3]);
    }
    __syncthreads();

    // ---- C2: weighted-popcount bound -> row flags ----
    for (int i = tid; i < R * NCH16; i += NTH) {
        const int r = i / NCH16;
        const int C = i - r * NCH16;
        float bsum = 0.0f;
#pragma unroll
        for (int d = 0; d < NDELTA; ++d) {
            const int c = C - d;
            if (c >= 0) bsum = fmaf(s_M[d], (float)cc[r * CCSTR + c], bsum);
        }
        if (bsum >= THETA - 0.02f) flag[r] = 1;   // benign same-value race
    }
    __syncthreads();

    if (tid < R && flag[tid] && (row0 + tid) < B) {
        const int p = atomicAdd(&nlist, 1);
        list[p] = (unsigned char)tid;
    }
    __syncthreads();

    // ---- Z: zero-fill unflagged rows (linear STG.128) ----
    float4* o4 = (float4*)out;
#pragma unroll
    for (int it = 0; it < ITERS; ++it) {
        const int idx = it * NTH + tid;
        const long long g = g4base + idx;
        const int r = idx / Q4;
        if (g < g4tot && !flag[r]) o4[g] = z;
    }

    // ---- S2/S3: flagged rows only ----
    if (tid < nlist) {
        const int r = list[tid];
        const int rowg = row0 + r;

        const double f1d = (double)srm[1];
        const double f2d = (double)srm[2];
        const double ddd = f2d / (2.0 * f1d);
        const double Add = f1d / ddd;
        const float dcy = (float)ddd;
        const float Af  = (float)Add;
        const float dK  = exp2f((float)Ksrm * log2f(dcy));
        const float C2c = Af * dK;
        const float C1c = Af * (float)Ksrm * dK;

        const float* xr = x + (size_t)rowg * T_LEN;

        // S2: exact truncated-u max (same FMA sequence as the scan's u)
        float s1 = 0.0f, s2 = 0.0f, s1d = 0.0f, s2d = 0.0f, mx = -1e30f;
#pragma unroll 4
        for (int t = 0; t < T_LEN; ++t) {
            const float xv = xr[t];
            const int j2 = t - Ksrm;
            const float xd = (j2 >= 0) ? xr[j2] : 0.0f;
            s2  = dcy * (s2 + s1);
            s1  = fmaf(dcy, s1, xv);
            s2d = dcy * (s2d + s1d);
            s1d = fmaf(dcy, s1d, xd);
            const float u = fmaf(-C1c, s1d, fmaf(-C2c, s2d, Af * s2));
            mx = fmaxf(mx, u);
        }

        float4* orow4 = (float4*)(out + (size_t)rowg * T_LEN);
        if (mx < THETA) {
            for (int q = 0; q < Q4; ++q) orow4[q] = z;
        } else {
            // S3: full exact scan (R1/R2 arithmetic; rel_err == 0 three times)
            float* orow = out + (size_t)rowg * T_LEN;
            s1 = s2 = s1d = s2d = 0.0f;
            float p[PENDN];
#pragma unroll
            for (int j = 0; j < PENDN; ++j) p[j] = 0.0f;

            for (int t = 0; t < T_LEN; ++t) {
                const float xv = xr[t];
                const int j2 = t - Ksrm;
                const float xd = (j2 >= 0) ? xr[j2] : 0.0f;

                s2  = dcy * (s2 + s1);
                s1  = fmaf(dcy, s1, xv);
                s2d = dcy * (s2d + s1d);
                s1d = fmaf(dcy, s1d, xd);

                const float u    = fmaf(-C1c, s1d, fmaf(-C2c, s2d, Af * s2));
                const float ueff = u + p[0];
                const float s    = (ueff >= THETA) ? 1.0f : 0.0f;

#pragma unroll
                for (int j = 0; j < PENDN - 1; ++j)
                    p[j] = fmaf(s, s_rt[j], p[j + 1]);
                p[PENDN - 1] = s * s_rt[PENDN - 1];

                orow[t] = s;
            }
        }
    }
}

extern "C" void kernel_launch(void* const* d_in, const int* in_sizes, int n_in,
                              void* d_out, int out_size)
{
    const float* x    = (const float*)d_in[0];
    const float* srm  = (const float*)d_in[1];
    const float* refk = (const float*)d_in[2];
    float* out        = (float*)d_out;

    const int total = in_sizes[0];
    const int B     = total / T_LEN;
    const int Ksrm  = in_sizes[1];
    const int Kref  = in_sizes[2];

    const int grid = (B + R - 1) / R;
    snn_r6_kernel<<<grid, NTH>>>(x, srm, refk, out, B, Ksrm, Kref);
}